// round 2
// baseline (speedup 1.0000x reference)
#include <cuda_runtime.h>
#include <cstdint>

#define NN      100000
#define D       256
#define BM      128
#define BN      64
#define BK      32

// Scratch for the SpMM result (side embeddings). 100000*256 fp32 = 102.4 MB.
__device__ float g_side[(size_t)NN * D];

// ---------------------------------------------------------------------------
// Scatter kernel: one warp per edge (grid-stride over edges).
//   side[rows[e], :] += vals[e] * ego[cols[e], :]
// Each lane handles 2 float4 (8 floats) of the 256-wide row.
// Uses red.global.add.v4.f32 (sm_90+) to quarter the L2 atomic op count.
// ---------------------------------------------------------------------------
__global__ void __launch_bounds__(256) scatter_k(
    const float4* __restrict__ ego4,
    const float*  __restrict__ vals,
    const int*    __restrict__ rows,
    const int*    __restrict__ cols,
    int E)
{
    const int lane    = threadIdx.x & 31;
    const int warp_id = (blockIdx.x * blockDim.x + threadIdx.x) >> 5;
    const int n_warps = (gridDim.x * blockDim.x) >> 5;

    for (int e = warp_id; e < E; e += n_warps) {
        int   c = __ldg(&cols[e]);
        int   r = __ldg(&rows[e]);
        float v = __ldg(&vals[e]);

        const float4* src = ego4 + (size_t)c * (D / 4);
        float*        dst = g_side + (size_t)r * D;

#pragma unroll
        for (int i = 0; i < 2; ++i) {
            float4 x = src[lane + 32 * i];
            float* p = dst + (size_t)(lane + 32 * i) * 4;
            asm volatile(
                "red.global.add.v4.f32 [%0], {%1, %2, %3, %4};"
                :: "l"(p), "f"(x.x * v), "f"(x.y * v), "f"(x.z * v), "f"(x.w * v)
                : "memory");
        }
    }
}

// ---------------------------------------------------------------------------
// Fused dual GEMM + bi-interaction epilogue:
//   out = lrelu((ego+side) @ W1 + b1) + lrelu((ego*side) @ W2 + b2)
// Tiling: BM=128 rows x BN=64 cols per block, K stepped in BK=32 chunks.
// 256 threads, each computes an 8x4 micro-tile for BOTH gemms.
// A-tiles (S = ego+side, P = ego*side) built on the fly from one read of
// ego and side each.
// ---------------------------------------------------------------------------
__device__ __forceinline__ float lrelu(float x) {
    // slope 0.01 < 1 so max(x, 0.01x) is exact for both signs
    return fmaxf(x, 0.01f * x);
}

__global__ void __launch_bounds__(256) fused_gemm_k(
    const float* __restrict__ ego,
    const float* __restrict__ W1, const float* __restrict__ b1,
    const float* __restrict__ W2, const float* __restrict__ b2,
    float* __restrict__ out, int n)
{
    // A tiles row-major [m][k]; B tiles k-major [k][n]. Exactly 48 KB total.
    __shared__ float sS[BM][BK];
    __shared__ float sP[BM][BK];
    __shared__ float sB1[BK][BN];
    __shared__ float sB2[BK][BN];

    const int t  = threadIdx.x;
    const int tx = t & 15;    // column group: cols tx*4 .. tx*4+3
    const int ty = t >> 4;    // row group:    rows ty*8 .. ty*8+7
    const int m0 = blockIdx.y * BM;
    const int n0 = blockIdx.x * BN;

    float acc1[8][4];
    float acc2[8][4];
#pragma unroll
    for (int i = 0; i < 8; ++i)
#pragma unroll
        for (int j = 0; j < 4; ++j) { acc1[i][j] = 0.0f; acc2[i][j] = 0.0f; }

    for (int k0 = 0; k0 < D; k0 += BK) {
        // ---- load A tiles: BM*BK = 4096 floats = 1024 float4; 4 per thread
#pragma unroll
        for (int j = 0; j < 4; ++j) {
            int idx = t + j * 256;          // 0..1023
            int row = idx >> 3;             // 0..127
            int kq  = idx & 7;              // float4 index in k
            int m   = m0 + row;
            float4 e4 = make_float4(0.f, 0.f, 0.f, 0.f);
            float4 s4 = make_float4(0.f, 0.f, 0.f, 0.f);
            if (m < n) {
                e4 = *reinterpret_cast<const float4*>(ego    + (size_t)m * D + k0 + kq * 4);
                s4 = *reinterpret_cast<const float4*>(g_side + (size_t)m * D + k0 + kq * 4);
            }
            float4 sum4 = make_float4(e4.x + s4.x, e4.y + s4.y, e4.z + s4.z, e4.w + s4.w);
            float4 prd4 = make_float4(e4.x * s4.x, e4.y * s4.y, e4.z * s4.z, e4.w * s4.w);
            *reinterpret_cast<float4*>(&sS[row][kq * 4]) = sum4;
            *reinterpret_cast<float4*>(&sP[row][kq * 4]) = prd4;
        }
        // ---- load B tiles: BK*BN = 2048 floats = 512 float4; 2 per thread per W
#pragma unroll
        for (int j = 0; j < 2; ++j) {
            int idx = t + j * 256;          // 0..511
            int kk  = idx >> 4;             // 0..31
            int nq  = idx & 15;             // float4 index in n
            *reinterpret_cast<float4*>(&sB1[kk][nq * 4]) =
                *reinterpret_cast<const float4*>(W1 + (size_t)(k0 + kk) * D + n0 + nq * 4);
            *reinterpret_cast<float4*>(&sB2[kk][nq * 4]) =
                *reinterpret_cast<const float4*>(W2 + (size_t)(k0 + kk) * D + n0 + nq * 4);
        }
        __syncthreads();

        // ---- compute
#pragma unroll
        for (int k = 0; k < BK; ++k) {
            float aS[8], aP[8], bb1[4], bb2[4];
#pragma unroll
            for (int i = 0; i < 8; ++i) {
                aS[i] = sS[ty * 8 + i][k];
                aP[i] = sP[ty * 8 + i][k];
            }
            *reinterpret_cast<float4*>(&bb1[0]) = *reinterpret_cast<float4*>(&sB1[k][tx * 4]);
            *reinterpret_cast<float4*>(&bb2[0]) = *reinterpret_cast<float4*>(&sB2[k][tx * 4]);
#pragma unroll
            for (int i = 0; i < 8; ++i)
#pragma unroll
                for (int j = 0; j < 4; ++j) {
                    acc1[i][j] = fmaf(aS[i], bb1[j], acc1[i][j]);
                    acc2[i][j] = fmaf(aP[i], bb2[j], acc2[i][j]);
                }
        }
        __syncthreads();
    }

    // ---- epilogue: bias + leaky relu + sum, vectorized store
    float bb1[4], bb2[4];
    *reinterpret_cast<float4*>(&bb1[0]) = *reinterpret_cast<const float4*>(b1 + n0 + tx * 4);
    *reinterpret_cast<float4*>(&bb2[0]) = *reinterpret_cast<const float4*>(b2 + n0 + tx * 4);

#pragma unroll
    for (int i = 0; i < 8; ++i) {
        int m = m0 + ty * 8 + i;
        if (m >= n) continue;
        float4 o;
        o.x = lrelu(acc1[i][0] + bb1[0]) + lrelu(acc2[i][0] + bb2[0]);
        o.y = lrelu(acc1[i][1] + bb1[1]) + lrelu(acc2[i][1] + bb2[1]);
        o.z = lrelu(acc1[i][2] + bb1[2]) + lrelu(acc2[i][2] + bb2[2]);
        o.w = lrelu(acc1[i][3] + bb1[3]) + lrelu(acc2[i][3] + bb2[3]);
        *reinterpret_cast<float4*>(out + (size_t)m * D + n0 + tx * 4) = o;
    }
}

// ---------------------------------------------------------------------------
extern "C" void kernel_launch(void* const* d_in, const int* in_sizes, int n_in,
                              void* d_out, int out_size)
{
    const float* ego  = (const float*)d_in[0];
    const float* vals = (const float*)d_in[1];
    const float* W1   = (const float*)d_in[2];
    const float* b1   = (const float*)d_in[3];
    const float* W2   = (const float*)d_in[4];
    const float* b2   = (const float*)d_in[5];
    const int*   rows = (const int*)d_in[6];
    const int*   cols = (const int*)d_in[7];
    float*       out  = (float*)d_out;

    int n = in_sizes[0] / D;     // 100000
    int E = in_sizes[1];         // 1600000

    // zero the side scratch (graph-capturable async memset)
    void* side_ptr = nullptr;
    cudaGetSymbolAddress(&side_ptr, g_side);
    cudaMemsetAsync(side_ptr, 0, (size_t)n * D * sizeof(float), 0);

    // scatter: one warp per edge (grid-stride; cap grid at exactly E warps)
    {
        long long warps_needed = (long long)E;
        long long blocks = (warps_needed * 32 + 255) / 256;
        if (blocks > 2000000) blocks = 2000000;   // safety cap; loop covers rest
        scatter_k<<<(int)blocks, 256>>>((const float4*)ego, vals, rows, cols, E);
    }

    // fused dual GEMM + epilogue
    {
        dim3 grid(D / BN, (n + BM - 1) / BM);
        fused_gemm_k<<<grid, 256>>>(ego, W1, b1, W2, b2, out, n);
    }
}

// round 9
// speedup vs baseline: 2.1175x; 2.1175x over previous
#include <cuda_runtime.h>
#include <cuda_bf16.h>
#include <cstdint>

#define NN      100000
#define E_MAX   1700000
#define D       256
#define M_TILE  64
#define BK      64
#define NCHUNK  4            // 256 / BK
#define THREADS 512

// Smem layout (bytes). Rows padded 128B->144B so 8 consecutive rows hit
// distinct 16B bank groups (conflict-free ldmatrix).
#define ROWB       144
#define A_MAT_B    (M_TILE * ROWB)            // 9216
#define OFF_B      (4 * A_MAT_B)              // 36864
#define B_MAT_B    (256 * ROWB)               // 36864
#define SMEM_TOTAL (OFF_B + 4 * B_MAT_B)      // 184320
#define B_CHUNK_B  (4 * B_MAT_B)              // 147456 per K-chunk
#define OFF_O2     67584                      // 64*264*4 staging stride
#define O_ROWF     264                        // fp32 per staged row (256+8 pad)

// ---------------------------------------------------------------------------
// Global scratch (static __device__ only — allocation-guard safe)
// ---------------------------------------------------------------------------
__device__ float g_side[(size_t)NN * D];                        // 102.4 MB
__device__ __align__(16) unsigned char g_Bpack[NCHUNK * B_CHUNK_B]; // 576 KB
__device__ int g_cnt[NN];
__device__ int g_off[NN];
__device__ int g_cur[NN];
__device__ int g_bsum[256];
__device__ int g_boff[256];
__device__ int g_eidx[E_MAX];

// ---------------------------------------------------------------------------
// helpers
// ---------------------------------------------------------------------------
__device__ __forceinline__ uint32_t smem_u32(const void* p) {
    uint32_t a;
    asm("{ .reg .u64 t; cvta.to.shared.u64 t, %1; cvt.u32.u64 %0, t; }"
        : "=r"(a) : "l"(p));
    return a;
}
__device__ __forceinline__ void ldsm_x4(uint32_t* r, uint32_t addr) {
    asm volatile("ldmatrix.sync.aligned.m8n8.x4.shared.b16 {%0,%1,%2,%3}, [%4];"
        : "=r"(r[0]), "=r"(r[1]), "=r"(r[2]), "=r"(r[3]) : "r"(addr));
}
__device__ __forceinline__ void mma16816(float* d, const uint32_t* a, const uint32_t* b) {
    asm volatile("mma.sync.aligned.m16n8k16.row.col.f32.bf16.bf16.f32 "
        "{%0,%1,%2,%3}, {%4,%5,%6,%7}, {%8,%9}, {%0,%1,%2,%3};"
        : "+f"(d[0]), "+f"(d[1]), "+f"(d[2]), "+f"(d[3])
        : "r"(a[0]), "r"(a[1]), "r"(a[2]), "r"(a[3]), "r"(b[0]), "r"(b[1]));
}
__device__ __forceinline__ float lrelu(float x) { return fmaxf(x, 0.01f * x); }

__device__ __forceinline__ void split8(const float* f, uint4& hi, uint4& lo) {
    uint32_t h[8], l[8];
#pragma unroll
    for (int i = 0; i < 8; ++i) {
        __nv_bfloat16 hb = __float2bfloat16(f[i]);
        __nv_bfloat16 lb = __float2bfloat16(f[i] - __bfloat162float(hb));
        h[i] = (uint32_t)__bfloat16_as_ushort(hb);
        l[i] = (uint32_t)__bfloat16_as_ushort(lb);
    }
    hi.x = h[0] | (h[1] << 16); hi.y = h[2] | (h[3] << 16);
    hi.z = h[4] | (h[5] << 16); hi.w = h[6] | (h[7] << 16);
    lo.x = l[0] | (l[1] << 16); lo.y = l[2] | (l[3] << 16);
    lo.z = l[4] | (l[5] << 16); lo.w = l[6] | (l[7] << 16);
}

// ---------------------------------------------------------------------------
// Weight prepack: bf16 hi/lo split, [n][k] K-major rows padded to 144B,
// grouped [chunk][mat 0:W1h 1:W1l 2:W2h 3:W2l][n][·] — exact smem images.
// ---------------------------------------------------------------------------
__global__ void __launch_bounds__(256) prepack_k(
    const float* __restrict__ W1, const float* __restrict__ W2)
{
    int tid = blockIdx.x * blockDim.x + threadIdx.x;   // 0..131071
    int w = tid >> 16;
    int k = (tid >> 8) & 255;
    int n = tid & 255;
    const float* W = w ? W2 : W1;
    float x = W[k * 256 + n];
    __nv_bfloat16 hi = __float2bfloat16(x);
    __nv_bfloat16 lo = __float2bfloat16(x - __bfloat162float(hi));
    int c = k >> 6, kl = k & 63;
    size_t base = (size_t)c * B_CHUNK_B + (size_t)n * ROWB + kl * 2;
    *(__nv_bfloat16*)&g_Bpack[base + (size_t)(w * 2 + 0) * B_MAT_B] = hi;
    *(__nv_bfloat16*)&g_Bpack[base + (size_t)(w * 2 + 1) * B_MAT_B] = lo;
}

// ---------------------------------------------------------------------------
// CSR build: histogram -> exclusive scan (3 kernels) -> cursor fill
// ---------------------------------------------------------------------------
__global__ void __launch_bounds__(256) hist_k(const int* __restrict__ rows, int E)
{
    int stride = gridDim.x * blockDim.x;
    for (int e = blockIdx.x * blockDim.x + threadIdx.x; e < E; e += stride)
        atomicAdd(&g_cnt[rows[e]], 1);
}

__global__ void __launch_bounds__(512) scan1_k(int n)
{
    __shared__ int sh[512];
    int i = blockIdx.x * 512 + threadIdx.x;
    int v = (i < n) ? g_cnt[i] : 0;
    sh[threadIdx.x] = v;
    __syncthreads();
#pragma unroll
    for (int d = 1; d < 512; d <<= 1) {
        int t = (threadIdx.x >= d) ? sh[threadIdx.x - d] : 0;
        __syncthreads();
        sh[threadIdx.x] += t;
        __syncthreads();
    }
    if (i < n) g_off[i] = sh[threadIdx.x] - v;       // exclusive
    if (threadIdx.x == 511) g_bsum[blockIdx.x] = sh[511];
}

__global__ void __launch_bounds__(256) scan2_k(int nb)
{
    __shared__ int sh[256];
    int v = (threadIdx.x < nb) ? g_bsum[threadIdx.x] : 0;
    sh[threadIdx.x] = v;
    __syncthreads();
#pragma unroll
    for (int d = 1; d < 256; d <<= 1) {
        int t = (threadIdx.x >= d) ? sh[threadIdx.x - d] : 0;
        __syncthreads();
        sh[threadIdx.x] += t;
        __syncthreads();
    }
    if (threadIdx.x < nb) g_boff[threadIdx.x] = sh[threadIdx.x] - v;  // exclusive
}

__global__ void __launch_bounds__(512) scan3_k(int n)
{
    int i = blockIdx.x * 512 + threadIdx.x;
    if (i < n) g_off[i] += g_boff[blockIdx.x];
}

__global__ void __launch_bounds__(256) fill_k(const int* __restrict__ rows, int E)
{
    int stride = gridDim.x * blockDim.x;
    for (int e = blockIdx.x * blockDim.x + threadIdx.x; e < E; e += stride) {
        int r = rows[e];
        int p = atomicAdd(&g_cur[r], 1);
        g_eidx[g_off[r] + p] = e;
    }
}

// ---------------------------------------------------------------------------
// Gather SpMM: one warp per row. acc in registers, side written exactly once
// (no atomics, no prior memset needed).
// ---------------------------------------------------------------------------
__global__ void __launch_bounds__(256) spmm_k(
    const float4* __restrict__ ego4,
    const float*  __restrict__ vals,
    const int*    __restrict__ cols,
    int n)
{
    const int lane    = threadIdx.x & 31;
    const int warp_id = (blockIdx.x * blockDim.x + threadIdx.x) >> 5;
    const int n_warps = (gridDim.x * blockDim.x) >> 5;

    for (int r = warp_id; r < n; r += n_warps) {
        int start = g_off[r];
        int end   = start + g_cnt[r];
        float4 a0 = make_float4(0.f, 0.f, 0.f, 0.f);
        float4 a1 = make_float4(0.f, 0.f, 0.f, 0.f);
        for (int i = start; i < end; ++i) {
            int   e = g_eidx[i];              // broadcast load
            int   c = __ldg(&cols[e]);
            float v = __ldg(&vals[e]);
            const float4* src = ego4 + (size_t)c * (D / 4);
            float4 f0 = src[lane];
            float4 f1 = src[lane + 32];
            a0.x = fmaf(v, f0.x, a0.x); a0.y = fmaf(v, f0.y, a0.y);
            a0.z = fmaf(v, f0.z, a0.z); a0.w = fmaf(v, f0.w, a0.w);
            a1.x = fmaf(v, f1.x, a1.x); a1.y = fmaf(v, f1.y, a1.y);
            a1.z = fmaf(v, f1.z, a1.z); a1.w = fmaf(v, f1.w, a1.w);
        }
        float4* dst = (float4*)(g_side + (size_t)r * D);
        dst[lane]      = a0;
        dst[lane + 32] = a1;
    }
}

// ---------------------------------------------------------------------------
// Fused dual GEMM via mma.sync bf16 (3-term hi/lo split) — UNCHANGED from R6/R7.
//   acc_g = Ah@Bh + Al@Bh + Ah@Bl,  A in {S=ego+side, P=ego*side}, B in {W1,W2}
//   out = lrelu(acc1+b1) + lrelu(acc2+b2)
// CTA: 64 rows x 256 cols, 512 threads / 16 warps.
// warp w: g = w&1 (gemm), mq = (w>>1)&3 (16-row quarter), nh = w>>3 (128-col half)
// ---------------------------------------------------------------------------
__global__ void __launch_bounds__(THREADS, 1) fused_gemm_mma(
    const float* __restrict__ ego,
    const float* __restrict__ b1, const float* __restrict__ b2,
    float* __restrict__ out, int nrows)
{
    extern __shared__ char smem[];
    const uint32_t sm = smem_u32(smem);
    const int t    = threadIdx.x;
    const int warp = t >> 5;
    const int lane = t & 31;
    const int g  = warp & 1;
    const int mq = (warp >> 1) & 3;
    const int nh = warp >> 3;
    const int m0 = blockIdx.x * M_TILE;

    float acc[16][4];
#pragma unroll
    for (int j = 0; j < 16; ++j)
#pragma unroll
        for (int q = 0; q < 4; ++q) acc[j][q] = 0.0f;

    const uint32_t aBaseH = sm + (g * 2) * A_MAT_B
                          + (uint32_t)(mq * 16 + (lane & 15)) * ROWB
                          + (uint32_t)(lane >> 4) * 16;
    const uint32_t aBaseL = aBaseH + A_MAT_B;
    const uint32_t bBaseH = sm + OFF_B + (g * 2) * B_MAT_B
                          + (uint32_t)(nh * 128 + (lane & 7) + ((lane >> 4) << 3)) * ROWB
                          + (uint32_t)((lane >> 3) & 1) * 16;
    const uint32_t bBaseL = bBaseH + B_MAT_B;

    for (int c = 0; c < NCHUNK; ++c) {
        if (c > 0) __syncthreads();

        // ---- A tiles: thread -> (row = t>>3, 8-float k-group kg = t&7) ----
        {
            int row = t >> 3, kg = t & 7;
            int m = m0 + row;
            float S[8], P[8];
            if (m < nrows) {
                const float4* pe = (const float4*)(ego    + (size_t)m * D + c * BK + kg * 8);
                const float4* ps = (const float4*)(g_side + (size_t)m * D + c * BK + kg * 8);
                float4 e0 = pe[0], e1 = pe[1], s0 = ps[0], s1 = ps[1];
                S[0]=e0.x+s0.x; S[1]=e0.y+s0.y; S[2]=e0.z+s0.z; S[3]=e0.w+s0.w;
                S[4]=e1.x+s1.x; S[5]=e1.y+s1.y; S[6]=e1.z+s1.z; S[7]=e1.w+s1.w;
                P[0]=e0.x*s0.x; P[1]=e0.y*s0.y; P[2]=e0.z*s0.z; P[3]=e0.w*s0.w;
                P[4]=e1.x*s1.x; P[5]=e1.y*s1.y; P[6]=e1.z*s1.z; P[7]=e1.w*s1.w;
            } else {
#pragma unroll
                for (int i = 0; i < 8; ++i) { S[i] = 0.f; P[i] = 0.f; }
            }
            uint4 sh, sl, ph, pl;
            split8(S, sh, sl);
            split8(P, ph, pl);
            char* a = smem + row * ROWB + kg * 16;
            *(uint4*)(a + 0 * A_MAT_B) = sh;
            *(uint4*)(a + 1 * A_MAT_B) = sl;
            *(uint4*)(a + 2 * A_MAT_B) = ph;
            *(uint4*)(a + 3 * A_MAT_B) = pl;
        }
        // ---- B tiles: copy prepacked chunk image ----
        {
            const uint4* src = (const uint4*)(g_Bpack + (size_t)c * B_CHUNK_B);
            uint4* dst = (uint4*)(smem + OFF_B);
#pragma unroll
            for (int i = 0; i < B_CHUNK_B / 16 / THREADS; ++i)
                dst[t + i * THREADS] = src[t + i * THREADS];
        }
        __syncthreads();

        // ---- compute: 4 k16 steps ----
#pragma unroll
        for (int ks = 0; ks < 4; ++ks) {
            uint32_t koff = (uint32_t)ks * 32;
            uint32_t ah[4], al[4];
            ldsm_x4(ah, aBaseH + koff);
            ldsm_x4(al, aBaseL + koff);
#pragma unroll
            for (int nt = 0; nt < 8; ++nt) {
                uint32_t bh[4];
                ldsm_x4(bh, bBaseH + (uint32_t)nt * (16 * ROWB) + koff);
                mma16816(acc[2 * nt + 0], ah, bh + 0);
                mma16816(acc[2 * nt + 1], ah, bh + 2);
                mma16816(acc[2 * nt + 0], al, bh + 0);
                mma16816(acc[2 * nt + 1], al, bh + 2);
            }
#pragma unroll
            for (int nt = 0; nt < 8; ++nt) {
                uint32_t bl[4];
                ldsm_x4(bl, bBaseL + (uint32_t)nt * (16 * ROWB) + koff);
                mma16816(acc[2 * nt + 0], ah, bl + 0);
                mma16816(acc[2 * nt + 1], ah, bl + 2);
            }
        }
    }
    __syncthreads();

    // ---- stage lrelu(acc + bias) per gemm into smem ----
    {
        const float* bias = g ? b2 : b1;
        char* oBase = smem + (g ? OFF_O2 : 0);
        int r0 = mq * 16 + (lane >> 2);
#pragma unroll
        for (int j = 0; j < 16; ++j) {
            int c0 = nh * 128 + j * 8 + 2 * (lane & 3);
            float bb0 = bias[c0], bb1 = bias[c0 + 1];
            float2 v0 = make_float2(lrelu(acc[j][0] + bb0), lrelu(acc[j][1] + bb1));
            float2 v1 = make_float2(lrelu(acc[j][2] + bb0), lrelu(acc[j][3] + bb1));
            *(float2*)(oBase + ((size_t)r0 * O_ROWF + c0) * 4)       = v0;
            *(float2*)(oBase + ((size_t)(r0 + 8) * O_ROWF + c0) * 4) = v1;
        }
    }
    __syncthreads();

    // ---- combine + coalesced store ----
#pragma unroll
    for (int i = 0; i < (M_TILE * D / 4) / THREADS; ++i) {
        int idx = t + i * THREADS;
        int row = idx >> 6, cq = idx & 63;
        int m = m0 + row;
        if (m < nrows) {
            float4 x = *(float4*)(smem + ((size_t)row * O_ROWF + cq * 4) * 4);
            float4 y = *(float4*)(smem + OFF_O2 + ((size_t)row * O_ROWF + cq * 4) * 4);
            float4 o = make_float4(x.x + y.x, x.y + y.y, x.z + y.z, x.w + y.w);
            *(float4*)(out + (size_t)m * D + cq * 4) = o;
        }
    }
}

// ---------------------------------------------------------------------------
extern "C" void kernel_launch(void* const* d_in, const int* in_sizes, int n_in,
                              void* d_out, int out_size)
{
    const float* ego  = (const float*)d_in[0];
    const float* vals = (const float*)d_in[1];
    const float* W1   = (const float*)d_in[2];
    const float* b1   = (const float*)d_in[3];
    const float* W2   = (const float*)d_in[4];
    const float* b2   = (const float*)d_in[5];
    const int*   rows = (const int*)d_in[6];
    const int*   cols = (const int*)d_in[7];
    float*       out  = (float*)d_out;

    int n = in_sizes[0] / D;     // 100000
    int E = in_sizes[1];         // 1600000

    // zero CSR counters/cursors (graph-capturable)
    void *cnt_ptr = nullptr, *cur_ptr = nullptr;
    cudaGetSymbolAddress(&cnt_ptr, g_cnt);
    cudaGetSymbolAddress(&cur_ptr, g_cur);
    cudaMemsetAsync(cnt_ptr, 0, (size_t)n * sizeof(int), 0);
    cudaMemsetAsync(cur_ptr, 0, (size_t)n * sizeof(int), 0);

    // weight prepack (independent of CSR chain)
    prepack_k<<<512, 256>>>(W1, W2);

    // CSR build
    int eb = (E + 255) / 256; if (eb > 65535) eb = 65535;
    hist_k<<<eb, 256>>>(rows, E);
    int nb1 = (n + 511) / 512;               // 196 for n=100000 (<=256 req'd)
    scan1_k<<<nb1, 512>>>(n);
    scan2_k<<<1, 256>>>(nb1);
    scan3_k<<<nb1, 512>>>(n);
    fill_k<<<eb, 256>>>(rows, E);

    // gather SpMM (one warp per row)
    {
        int blocks = (n * 32 + 255) / 256;
        spmm_k<<<blocks, 256>>>((const float4*)ego, vals, cols, n);
    }

    // fused dual GEMM (mma.sync bf16, 3-term split)
    cudaFuncSetAttribute(fused_gemm_mma,
                         cudaFuncAttributeMaxDynamicSharedMemorySize, SMEM_TOTAL);
    {
        int grid = (n + M_TILE - 1) / M_TILE;
        fused_gemm_mma<<<grid, THREADS, SMEM_TOTAL>>>(ego, b1, b2, out, n);
    }
}

// round 11
// speedup vs baseline: 2.4197x; 1.1427x over previous
#include <cuda_runtime.h>
#include <cuda_bf16.h>
#include <cstdint>

#define NN      100000
#define E_MAX   1700000
#define D       256
#define M_TILE  64
#define BK      64
#define NCHUNK  4            // 256 / BK
#define THREADS 512

// Smem layout (bytes). Rows padded 128B->144B so 8 consecutive rows hit
// distinct 16B bank groups (conflict-free ldmatrix).
#define ROWB       144
#define A_MAT_B    (M_TILE * ROWB)            // 9216
#define OFF_B      (4 * A_MAT_B)              // 36864
#define B_MAT_B    (256 * ROWB)               // 36864
#define SMEM_TOTAL (OFF_B + 4 * B_MAT_B)      // 184320
#define B_CHUNK_B  (4 * B_MAT_B)              // 147456 per K-chunk
#define OFF_O2     67584                      // 64*264*4 staging stride
#define O_ROWF     264                        // fp32 per staged row (256+8 pad)

// ---------------------------------------------------------------------------
// Global scratch (static __device__ only — allocation-guard safe)
// ---------------------------------------------------------------------------
__device__ float g_side[(size_t)NN * D];                        // 102.4 MB
__device__ __align__(16) unsigned char g_Bpack[NCHUNK * B_CHUNK_B]; // 576 KB
__device__ int g_cnt[NN];
__device__ int g_off[NN];
__device__ int g_cur[NN];
__device__ int g_bsum[256];
__device__ int g_boff[256];
__device__ int g_eidx[E_MAX];

// ---------------------------------------------------------------------------
// helpers
// ---------------------------------------------------------------------------
__device__ __forceinline__ uint32_t smem_u32(const void* p) {
    uint32_t a;
    asm("{ .reg .u64 t; cvta.to.shared.u64 t, %1; cvt.u32.u64 %0, t; }"
        : "=r"(a) : "l"(p));
    return a;
}
__device__ __forceinline__ void ldsm_x4(uint32_t* r, uint32_t addr) {
    asm volatile("ldmatrix.sync.aligned.m8n8.x4.shared.b16 {%0,%1,%2,%3}, [%4];"
        : "=r"(r[0]), "=r"(r[1]), "=r"(r[2]), "=r"(r[3]) : "r"(addr));
}
__device__ __forceinline__ void mma16816(float* d, const uint32_t* a, const uint32_t* b) {
    asm volatile("mma.sync.aligned.m16n8k16.row.col.f32.bf16.bf16.f32 "
        "{%0,%1,%2,%3}, {%4,%5,%6,%7}, {%8,%9}, {%0,%1,%2,%3};"
        : "+f"(d[0]), "+f"(d[1]), "+f"(d[2]), "+f"(d[3])
        : "r"(a[0]), "r"(a[1]), "r"(a[2]), "r"(a[3]), "r"(b[0]), "r"(b[1]));
}
__device__ __forceinline__ void cp_async16(uint32_t dst, const void* src) {
    asm volatile("cp.async.cg.shared.global [%0], [%1], 16;"
        :: "r"(dst), "l"(src) : "memory");
}
#define CP_COMMIT() asm volatile("cp.async.commit_group;" ::: "memory")
#define CP_WAIT0()  asm volatile("cp.async.wait_group 0;" ::: "memory")

__device__ __forceinline__ float lrelu(float x) { return fmaxf(x, 0.01f * x); }

__device__ __forceinline__ void split8(const float* f, uint4& hi, uint4& lo) {
    uint32_t h[8], l[8];
#pragma unroll
    for (int i = 0; i < 8; ++i) {
        __nv_bfloat16 hb = __float2bfloat16(f[i]);
        __nv_bfloat16 lb = __float2bfloat16(f[i] - __bfloat162float(hb));
        h[i] = (uint32_t)__bfloat16_as_ushort(hb);
        l[i] = (uint32_t)__bfloat16_as_ushort(lb);
    }
    hi.x = h[0] | (h[1] << 16); hi.y = h[2] | (h[3] << 16);
    hi.z = h[4] | (h[5] << 16); hi.w = h[6] | (h[7] << 16);
    lo.x = l[0] | (l[1] << 16); lo.y = l[2] | (l[3] << 16);
    lo.z = l[4] | (l[5] << 16); lo.w = l[6] | (l[7] << 16);
}

// ---------------------------------------------------------------------------
// Weight prepack: bf16 hi/lo split, [n][k] K-major rows padded to 144B,
// grouped [chunk][mat 0:W1h 1:W1l 2:W2h 3:W2l][n][·] — exact smem images.
// ---------------------------------------------------------------------------
__global__ void __launch_bounds__(256) prepack_k(
    const float* __restrict__ W1, const float* __restrict__ W2)
{
    int tid = blockIdx.x * blockDim.x + threadIdx.x;   // 0..131071
    int w = tid >> 16;
    int k = (tid >> 8) & 255;
    int n = tid & 255;
    const float* W = w ? W2 : W1;
    float x = W[k * 256 + n];
    __nv_bfloat16 hi = __float2bfloat16(x);
    __nv_bfloat16 lo = __float2bfloat16(x - __bfloat162float(hi));
    int c = k >> 6, kl = k & 63;
    size_t base = (size_t)c * B_CHUNK_B + (size_t)n * ROWB + kl * 2;
    *(__nv_bfloat16*)&g_Bpack[base + (size_t)(w * 2 + 0) * B_MAT_B] = hi;
    *(__nv_bfloat16*)&g_Bpack[base + (size_t)(w * 2 + 1) * B_MAT_B] = lo;
}

// ---------------------------------------------------------------------------
// CSR build: histogram -> exclusive scan (3 kernels) -> cursor fill
// ---------------------------------------------------------------------------
__global__ void __launch_bounds__(256) hist_k(const int* __restrict__ rows, int E)
{
    int stride = gridDim.x * blockDim.x;
    for (int e = blockIdx.x * blockDim.x + threadIdx.x; e < E; e += stride)
        atomicAdd(&g_cnt[rows[e]], 1);
}

__global__ void __launch_bounds__(512) scan1_k(int n)
{
    __shared__ int sh[512];
    int i = blockIdx.x * 512 + threadIdx.x;
    int v = (i < n) ? g_cnt[i] : 0;
    sh[threadIdx.x] = v;
    __syncthreads();
#pragma unroll
    for (int d = 1; d < 512; d <<= 1) {
        int t = (threadIdx.x >= d) ? sh[threadIdx.x - d] : 0;
        __syncthreads();
        sh[threadIdx.x] += t;
        __syncthreads();
    }
    if (i < n) g_off[i] = sh[threadIdx.x] - v;       // exclusive
    if (threadIdx.x == 511) g_bsum[blockIdx.x] = sh[511];
}

__global__ void __launch_bounds__(256) scan2_k(int nb)
{
    __shared__ int sh[256];
    int v = (threadIdx.x < nb) ? g_bsum[threadIdx.x] : 0;
    sh[threadIdx.x] = v;
    __syncthreads();
#pragma unroll
    for (int d = 1; d < 256; d <<= 1) {
        int t = (threadIdx.x >= d) ? sh[threadIdx.x - d] : 0;
        __syncthreads();
        sh[threadIdx.x] += t;
        __syncthreads();
    }
    if (threadIdx.x < nb) g_boff[threadIdx.x] = sh[threadIdx.x] - v;  // exclusive
}

__global__ void __launch_bounds__(512) scan3_k(int n)
{
    int i = blockIdx.x * 512 + threadIdx.x;
    if (i < n) g_off[i] += g_boff[blockIdx.x];
}

__global__ void __launch_bounds__(256) fill_k(const int* __restrict__ rows, int E)
{
    int stride = gridDim.x * blockDim.x;
    for (int e = blockIdx.x * blockDim.x + threadIdx.x; e < E; e += stride) {
        int r = rows[e];
        int p = atomicAdd(&g_cur[r], 1);
        g_eidx[g_off[r] + p] = e;
    }
}

// ---------------------------------------------------------------------------
// Gather SpMM: one warp per row, 2-edge unroll for MLP. side written once.
// ---------------------------------------------------------------------------
__global__ void __launch_bounds__(256) spmm_k(
    const float4* __restrict__ ego4,
    const float*  __restrict__ vals,
    const int*    __restrict__ cols,
    int n)
{
    const int lane    = threadIdx.x & 31;
    const int warp_id = (blockIdx.x * blockDim.x + threadIdx.x) >> 5;
    const int n_warps = (gridDim.x * blockDim.x) >> 5;

    for (int r = warp_id; r < n; r += n_warps) {
        int start = g_off[r];
        int end   = start + g_cnt[r];
        float4 a0 = make_float4(0.f, 0.f, 0.f, 0.f);
        float4 a1 = make_float4(0.f, 0.f, 0.f, 0.f);
        int i = start;
        for (; i + 1 < end; i += 2) {
            int   e0 = g_eidx[i],     e1 = g_eidx[i + 1];
            int   c0 = __ldg(&cols[e0]), c1 = __ldg(&cols[e1]);
            float v0 = __ldg(&vals[e0]), v1 = __ldg(&vals[e1]);
            const float4* s0 = ego4 + (size_t)c0 * (D / 4);
            const float4* s1 = ego4 + (size_t)c1 * (D / 4);
            float4 p0 = s0[lane], p1 = s0[lane + 32];
            float4 q0 = s1[lane], q1 = s1[lane + 32];
            a0.x = fmaf(v0, p0.x, a0.x); a0.y = fmaf(v0, p0.y, a0.y);
            a0.z = fmaf(v0, p0.z, a0.z); a0.w = fmaf(v0, p0.w, a0.w);
            a1.x = fmaf(v0, p1.x, a1.x); a1.y = fmaf(v0, p1.y, a1.y);
            a1.z = fmaf(v0, p1.z, a1.z); a1.w = fmaf(v0, p1.w, a1.w);
            a0.x = fmaf(v1, q0.x, a0.x); a0.y = fmaf(v1, q0.y, a0.y);
            a0.z = fmaf(v1, q0.z, a0.z); a0.w = fmaf(v1, q0.w, a0.w);
            a1.x = fmaf(v1, q1.x, a1.x); a1.y = fmaf(v1, q1.y, a1.y);
            a1.z = fmaf(v1, q1.z, a1.z); a1.w = fmaf(v1, q1.w, a1.w);
        }
        if (i < end) {
            int   e = g_eidx[i];
            int   c = __ldg(&cols[e]);
            float v = __ldg(&vals[e]);
            const float4* src = ego4 + (size_t)c * (D / 4);
            float4 f0 = src[lane], f1 = src[lane + 32];
            a0.x = fmaf(v, f0.x, a0.x); a0.y = fmaf(v, f0.y, a0.y);
            a0.z = fmaf(v, f0.z, a0.z); a0.w = fmaf(v, f0.w, a0.w);
            a1.x = fmaf(v, f1.x, a1.x); a1.y = fmaf(v, f1.y, a1.y);
            a1.z = fmaf(v, f1.z, a1.z); a1.w = fmaf(v, f1.w, a1.w);
        }
        float4* dst = (float4*)(g_side + (size_t)r * D);
        dst[lane]      = a0;
        dst[lane + 32] = a1;
    }
}

// ---------------------------------------------------------------------------
// Fused dual GEMM via mma.sync bf16 (3-term hi/lo split), cp.async B pipeline:
//   per chunk: issue B cp.async (async) -> A fill math overlaps -> wait -> mma
// ---------------------------------------------------------------------------
__global__ void __launch_bounds__(THREADS, 1) fused_gemm_mma(
    const float* __restrict__ ego,
    const float* __restrict__ b1, const float* __restrict__ b2,
    float* __restrict__ out, int nrows)
{
    extern __shared__ char smem[];
    const uint32_t sm = smem_u32(smem);
    const int t    = threadIdx.x;
    const int warp = t >> 5;
    const int lane = t & 31;
    const int g  = warp & 1;
    const int mq = (warp >> 1) & 3;
    const int nh = warp >> 3;
    const int m0 = blockIdx.x * M_TILE;

    float acc[16][4];
#pragma unroll
    for (int j = 0; j < 16; ++j)
#pragma unroll
        for (int q = 0; q < 4; ++q) acc[j][q] = 0.0f;

    const uint32_t aBaseH = sm + (g * 2) * A_MAT_B
                          + (uint32_t)(mq * 16 + (lane & 15)) * ROWB
                          + (uint32_t)(lane >> 4) * 16;
    const uint32_t aBaseL = aBaseH + A_MAT_B;
    const uint32_t bBaseH = sm + OFF_B + (g * 2) * B_MAT_B
                          + (uint32_t)(nh * 128 + (lane & 7) + ((lane >> 4) << 3)) * ROWB
                          + (uint32_t)((lane >> 3) & 1) * 16;
    const uint32_t bBaseL = bBaseH + B_MAT_B;

    for (int c = 0; c < NCHUNK; ++c) {
        if (c > 0) __syncthreads();          // prior chunk fully consumed

        // ---- B tiles: async copy of prepacked chunk image (overlaps A fill) ----
        {
            const char* src = (const char*)(g_Bpack + (size_t)c * B_CHUNK_B);
            uint32_t dstBase = sm + OFF_B;
#pragma unroll
            for (int i = 0; i < B_CHUNK_B / 16 / THREADS; ++i) {
                uint32_t off = (uint32_t)(t + i * THREADS) * 16;
                cp_async16(dstBase + off, src + off);
            }
            CP_COMMIT();
        }

        // ---- A tiles: thread -> (row = t>>3, 8-float k-group kg = t&7) ----
        {
            int row = t >> 3, kg = t & 7;
            int m = m0 + row;
            float S[8], P[8];
            if (m < nrows) {
                const float4* pe = (const float4*)(ego    + (size_t)m * D + c * BK + kg * 8);
                const float4* ps = (const float4*)(g_side + (size_t)m * D + c * BK + kg * 8);
                float4 e0 = pe[0], e1 = pe[1], s0 = ps[0], s1 = ps[1];
                S[0]=e0.x+s0.x; S[1]=e0.y+s0.y; S[2]=e0.z+s0.z; S[3]=e0.w+s0.w;
                S[4]=e1.x+s1.x; S[5]=e1.y+s1.y; S[6]=e1.z+s1.z; S[7]=e1.w+s1.w;
                P[0]=e0.x*s0.x; P[1]=e0.y*s0.y; P[2]=e0.z*s0.z; P[3]=e0.w*s0.w;
                P[4]=e1.x*s1.x; P[5]=e1.y*s1.y; P[6]=e1.z*s1.z; P[7]=e1.w*s1.w;
            } else {
#pragma unroll
                for (int i = 0; i < 8; ++i) { S[i] = 0.f; P[i] = 0.f; }
            }
            uint4 sh, sl, ph, pl;
            split8(S, sh, sl);
            split8(P, ph, pl);
            char* a = smem + row * ROWB + kg * 16;
            *(uint4*)(a + 0 * A_MAT_B) = sh;
            *(uint4*)(a + 1 * A_MAT_B) = sl;
            *(uint4*)(a + 2 * A_MAT_B) = ph;
            *(uint4*)(a + 3 * A_MAT_B) = pl;
        }
        CP_WAIT0();
        __syncthreads();

        // ---- compute: 4 k16 steps ----
#pragma unroll
        for (int ks = 0; ks < 4; ++ks) {
            uint32_t koff = (uint32_t)ks * 32;
            uint32_t ah[4], al[4];
            ldsm_x4(ah, aBaseH + koff);
            ldsm_x4(al, aBaseL + koff);
#pragma unroll
            for (int nt = 0; nt < 8; ++nt) {
                uint32_t bh[4];
                ldsm_x4(bh, bBaseH + (uint32_t)nt * (16 * ROWB) + koff);
                mma16816(acc[2 * nt + 0], ah, bh + 0);
                mma16816(acc[2 * nt + 1], ah, bh + 2);
                mma16816(acc[2 * nt + 0], al, bh + 0);
                mma16816(acc[2 * nt + 1], al, bh + 2);
            }
#pragma unroll
            for (int nt = 0; nt < 8; ++nt) {
                uint32_t bl[4];
                ldsm_x4(bl, bBaseL + (uint32_t)nt * (16 * ROWB) + koff);
                mma16816(acc[2 * nt + 0], ah, bl + 0);
                mma16816(acc[2 * nt + 1], ah, bl + 2);
            }
        }
    }
    __syncthreads();

    // ---- stage lrelu(acc + bias) per gemm into smem ----
    {
        const float* bias = g ? b2 : b1;
        char* oBase = smem + (g ? OFF_O2 : 0);
        int r0 = mq * 16 + (lane >> 2);
#pragma unroll
        for (int j = 0; j < 16; ++j) {
            int c0 = nh * 128 + j * 8 + 2 * (lane & 3);
            float bb0 = bias[c0], bb1 = bias[c0 + 1];
            float2 v0 = make_float2(lrelu(acc[j][0] + bb0), lrelu(acc[j][1] + bb1));
            float2 v1 = make_float2(lrelu(acc[j][2] + bb0), lrelu(acc[j][3] + bb1));
            *(float2*)(oBase + ((size_t)r0 * O_ROWF + c0) * 4)       = v0;
            *(float2*)(oBase + ((size_t)(r0 + 8) * O_ROWF + c0) * 4) = v1;
        }
    }
    __syncthreads();

    // ---- combine + coalesced store ----
#pragma unroll
    for (int i = 0; i < (M_TILE * D / 4) / THREADS; ++i) {
        int idx = t + i * THREADS;
        int row = idx >> 6, cq = idx & 63;
        int m = m0 + row;
        if (m < nrows) {
            float4 x = *(float4*)(smem + ((size_t)row * O_ROWF + cq * 4) * 4);
            float4 y = *(float4*)(smem + OFF_O2 + ((size_t)row * O_ROWF + cq * 4) * 4);
            float4 o = make_float4(x.x + y.x, x.y + y.y, x.z + y.z, x.w + y.w);
            *(float4*)(out + (size_t)m * D + cq * 4) = o;
        }
    }
}

// ---------------------------------------------------------------------------
extern "C" void kernel_launch(void* const* d_in, const int* in_sizes, int n_in,
                              void* d_out, int out_size)
{
    const float* ego  = (const float*)d_in[0];
    const float* vals = (const float*)d_in[1];
    const float* W1   = (const float*)d_in[2];
    const float* b1   = (const float*)d_in[3];
    const float* W2   = (const float*)d_in[4];
    const float* b2   = (const float*)d_in[5];
    const int*   rows = (const int*)d_in[6];
    const int*   cols = (const int*)d_in[7];
    float*       out  = (float*)d_out;

    int n = in_sizes[0] / D;     // 100000
    int E = in_sizes[1];         // 1600000

    // zero CSR counters/cursors (graph-capturable)
    void *cnt_ptr = nullptr, *cur_ptr = nullptr;
    cudaGetSymbolAddress(&cnt_ptr, g_cnt);
    cudaGetSymbolAddress(&cur_ptr, g_cur);
    cudaMemsetAsync(cnt_ptr, 0, (size_t)n * sizeof(int), 0);
    cudaMemsetAsync(cur_ptr, 0, (size_t)n * sizeof(int), 0);

    // weight prepack (independent of CSR chain)
    prepack_k<<<512, 256>>>(W1, W2);

    // CSR build
    int eb = (E + 255) / 256; if (eb > 65535) eb = 65535;
    hist_k<<<eb, 256>>>(rows, E);
    int nb1 = (n + 511) / 512;               // 196 for n=100000 (<=256 req'd)
    scan1_k<<<nb1, 512>>>(n);
    scan2_k<<<1, 256>>>(nb1);
    scan3_k<<<nb1, 512>>>(n);
    fill_k<<<eb, 256>>>(rows, E);

    // gather SpMM (one warp per row)
    {
        int blocks = (n * 32 + 255) / 256;
        spmm_k<<<blocks, 256>>>((const float4*)ego, vals, cols, n);
    }

    // fused dual GEMM (mma.sync bf16, 3-term split, cp.async pipeline)
    cudaFuncSetAttribute(fused_gemm_mma,
                         cudaFuncAttributeMaxDynamicSharedMemorySize, SMEM_TOTAL);
    {
        int grid = (n + M_TILE - 1) / M_TILE;
        fused_gemm_mma<<<grid, THREADS, SMEM_TOTAL>>>(ego, b1, b2, out, n);
    }
}